// round 2
// baseline (speedup 1.0000x reference)
#include <cuda_runtime.h>
#include <cstdint>

#define BATCH   4
#define SEQ     4096
#define HID     2048
#define NHEADS  16
#define HDIM    128
#define MTOT    (BATCH*SEQ)   /* 16384 */
#define NQKV    (3*HID)       /* 6144  */

// Scratch (device globals; no runtime allocation allowed)
__device__ float g_qkv[(size_t)MTOT*NQKV];   // [b*4096+s][3*16*128]
__device__ float g_ctx[(size_t)MTOT*HID];    // permuted context rows for proj GEMM

__device__ __forceinline__ float tf32r(float x){
    unsigned u; asm("cvt.rna.tf32.f32 %0, %1;" : "=r"(u) : "f"(x));
    return __uint_as_float(u);
}

__device__ __forceinline__ void mma8(float* c, float a0,float a1,float a2,float a3,
                                     float b0,float b1){
    asm volatile("mma.sync.aligned.m16n8k8.row.col.f32.tf32.tf32.f32 "
        "{%0,%1,%2,%3},{%4,%5,%6,%7},{%8,%9},{%0,%1,%2,%3};"
        : "+f"(c[0]),"+f"(c[1]),"+f"(c[2]),"+f"(c[3])
        : "r"(__float_as_uint(a0)),"r"(__float_as_uint(a1)),
          "r"(__float_as_uint(a2)),"r"(__float_as_uint(a3)),
          "r"(__float_as_uint(b0)),"r"(__float_as_uint(b1)));
}

// ---------------------------------------------------------------------------
// 128x128x32 TF32 GEMM, C = A*B + bias.
// MODE 0: A = Ain (x), C -> g_qkv.   MODE 1: A = g_ctx, C -> Cout.
// ---------------------------------------------------------------------------
template<int MODE>
__global__ void __launch_bounds__(256)
gemm_kernel(const float* __restrict__ Ain, const float* __restrict__ B,
            const float* __restrict__ bias, float* __restrict__ Cout,
            int K, int N)
{
    const float* A = (MODE==1) ? (const float*)g_ctx : Ain;
    float* C       = (MODE==0) ? (float*)g_qkv : Cout;

    __shared__ float As[128][36];   // [m][k]
    __shared__ float Bs[32][132];   // [k][n]

    const int tid  = threadIdx.x;
    const int warp = tid>>5, lane = tid&31;
    const int g = lane>>2, t = lane&3;
    const int wm = warp>>2, wn = warp&3;           // 2 x 4 warps
    const int m0 = blockIdx.y*128, n0 = blockIdx.x*128;

    float acc[4][4][4];
    #pragma unroll
    for(int i=0;i<4;++i)
        #pragma unroll
        for(int j=0;j<4;++j)
            #pragma unroll
            for(int e=0;e<4;++e) acc[i][j][e]=0.f;

    float4 ra[4], rb[4];
    #pragma unroll
    for(int it=0; it<4; ++it){
        int idx = tid + 256*it;
        ra[it] = *(const float4*)(A + (size_t)(m0 + (idx>>3))*K + ((idx&7)<<2));
        rb[it] = *(const float4*)(B + (size_t)(idx>>5)*N + n0 + ((idx&31)<<2));
    }
    #pragma unroll
    for(int it=0; it<4; ++it){
        int idx = tid + 256*it;
        int r=idx>>3, c=(idx&7)<<2;
        As[r][c+0]=tf32r(ra[it].x); As[r][c+1]=tf32r(ra[it].y);
        As[r][c+2]=tf32r(ra[it].z); As[r][c+3]=tf32r(ra[it].w);
        int rk=idx>>5, cn=(idx&31)<<2;
        Bs[rk][cn+0]=tf32r(rb[it].x); Bs[rk][cn+1]=tf32r(rb[it].y);
        Bs[rk][cn+2]=tf32r(rb[it].z); Bs[rk][cn+3]=tf32r(rb[it].w);
    }
    __syncthreads();

    const int NK = K/32;
    for(int kt=0; kt<NK; ++kt){
        if (kt+1 < NK){
            int k0 = (kt+1)*32;
            #pragma unroll
            for(int it=0; it<4; ++it){
                int idx = tid + 256*it;
                ra[it] = *(const float4*)(A + (size_t)(m0 + (idx>>3))*K + k0 + ((idx&7)<<2));
                rb[it] = *(const float4*)(B + (size_t)(k0 + (idx>>5))*N + n0 + ((idx&31)<<2));
            }
        }
        #pragma unroll
        for(int ks=0; ks<4; ++ks){
            int kk = ks*8;
            float af[4][4], bf[4][2];
            #pragma unroll
            for(int i=0;i<4;++i){
                int rb0 = wm*64 + i*16;
                af[i][0]=As[rb0+g  ][kk+t  ];
                af[i][1]=As[rb0+g+8][kk+t  ];
                af[i][2]=As[rb0+g  ][kk+t+4];
                af[i][3]=As[rb0+g+8][kk+t+4];
            }
            #pragma unroll
            for(int j=0;j<4;++j){
                int cb = wn*32 + j*8 + g;
                bf[j][0]=Bs[kk+t  ][cb];
                bf[j][1]=Bs[kk+t+4][cb];
            }
            #pragma unroll
            for(int i=0;i<4;++i)
                #pragma unroll
                for(int j=0;j<4;++j)
                    mma8(acc[i][j], af[i][0],af[i][1],af[i][2],af[i][3],
                         bf[j][0],bf[j][1]);
        }
        if (kt+1 < NK){
            __syncthreads();
            #pragma unroll
            for(int it=0; it<4; ++it){
                int idx = tid + 256*it;
                int r=idx>>3, c=(idx&7)<<2;
                As[r][c+0]=tf32r(ra[it].x); As[r][c+1]=tf32r(ra[it].y);
                As[r][c+2]=tf32r(ra[it].z); As[r][c+3]=tf32r(ra[it].w);
                int rk=idx>>5, cn=(idx&31)<<2;
                Bs[rk][cn+0]=tf32r(rb[it].x); Bs[rk][cn+1]=tf32r(rb[it].y);
                Bs[rk][cn+2]=tf32r(rb[it].z); Bs[rk][cn+3]=tf32r(rb[it].w);
            }
            __syncthreads();
        }
    }

    // epilogue: pairs (c, c+1) as float2 stores
    #pragma unroll
    for(int i=0;i<4;++i){
        #pragma unroll
        for(int j=0;j<4;++j){
            int r0 = m0 + wm*64 + i*16 + g;
            int c0 = n0 + wn*32 + j*8 + 2*t;
            float2 b01 = make_float2(bias[c0], bias[c0+1]);
            float2 v0 = make_float2(acc[i][j][0]+b01.x, acc[i][j][1]+b01.y);
            float2 v1 = make_float2(acc[i][j][2]+b01.x, acc[i][j][3]+b01.y);
            *(float2*)(C + (size_t)r0*N + c0)     = v0;
            *(float2*)(C + (size_t)(r0+8)*N + c0) = v1;
        }
    }
}

// ---------------------------------------------------------------------------
// Per-position head-mixing "attention" (matches reference einsum exactly):
// for each (b,s): S[h][t] = q[h].k[t]/sqrt(128) over heads t, softmax over t,
// ctx[h] = sum_t w[h][t] v[t]. One CTA (128 thr) per position.
// Writes g_ctx in the reference's transpose(0,2,1,3).reshape layout:
//   row = b*4096 + h*256 + s/16, col = (s%16)*128 + d.
// ---------------------------------------------------------------------------
__global__ void __launch_bounds__(128)
attn_kernel()
{
    __shared__ float S[48*132];      // 48 rows (q0-15,k16-31,v32-47) x 128, pad 132

    const int tid = threadIdx.x;
    const size_t pos = blockIdx.x;               // b*4096 + s
    const float* row = g_qkv + pos*NQKV;

    #pragma unroll
    for(int it=0; it<12; ++it){
        int idx = tid + 128*it;                  // float4 index 0..1535
        int f = idx<<2;
        int r = f>>7, c = f&127;
        *(float4*)(S + r*132 + c) = *(const float4*)(row + f);
    }
    __syncthreads();

    const int h = tid>>3, i = tid&7;             // 16 heads x 8 lanes
    const float4* Q4 = (const float4*)(S + h*132);
    const float4* K0 = (const float4*)(S + (16+i)*132);
    const float4* K1 = (const float4*)(S + (24+i)*132);

    float s0=0.f, s1=0.f;
    #pragma unroll
    for(int d=0; d<32; ++d){
        float4 q = Q4[d], a = K0[d], b = K1[d];
        s0 += q.x*a.x + q.y*a.y + q.z*a.z + q.w*a.w;
        s1 += q.x*b.x + q.y*b.y + q.z*b.z + q.w*b.w;
    }
    const float sc = 0.08838834764831845f;       // 1/sqrt(128)
    s0 *= sc; s1 *= sc;

    float m = fmaxf(s0, s1);
    m = fmaxf(m, __shfl_xor_sync(0xffffffffu, m, 1));
    m = fmaxf(m, __shfl_xor_sync(0xffffffffu, m, 2));
    m = fmaxf(m, __shfl_xor_sync(0xffffffffu, m, 4));
    float e0 = __expf(s0 - m), e1 = __expf(s1 - m);
    float sum = e0 + e1;
    sum += __shfl_xor_sync(0xffffffffu, sum, 1);
    sum += __shfl_xor_sync(0xffffffffu, sum, 2);
    sum += __shfl_xor_sync(0xffffffffu, sum, 4);
    float inv = 1.f/sum;
    float w0 = e0*inv, w1 = e1*inv;

    float wv[16];
    #pragma unroll
    for(int j=0;j<8;++j){
        wv[j]   = __shfl_sync(0xffffffffu, w0, j, 8);
        wv[j+8] = __shfl_sync(0xffffffffu, w1, j, 8);
    }

    const int b = (int)(pos>>12), s = (int)(pos&4095);
    float* orow = g_ctx + ((size_t)(b*SEQ + h*256 + (s>>4)))*HID + (size_t)(s&15)*HDIM;
    #pragma unroll
    for(int j=0;j<4;++j){
        int d4 = i + 8*j;                        // float4 column within 128-d
        float4 acc = make_float4(0.f,0.f,0.f,0.f);
        #pragma unroll
        for(int t=0;t<16;++t){
            float4 v = *(const float4*)(S + (32+t)*132 + (d4<<2));
            acc.x += wv[t]*v.x; acc.y += wv[t]*v.y;
            acc.z += wv[t]*v.z; acc.w += wv[t]*v.w;
        }
        *(float4*)(orow + (d4<<2)) = acc;
    }
}

// ---------------------------------------------------------------------------
extern "C" void kernel_launch(void* const* d_in, const int* in_sizes, int n_in,
                              void* d_out, int out_size)
{
    const float* x     = (const float*)d_in[0];
    const float* Wqkv  = (const float*)d_in[1];
    const float* bqkv  = (const float*)d_in[2];
    const float* Wproj = (const float*)d_in[3];
    const float* bproj = (const float*)d_in[4];
    float* out = (float*)d_out;

    gemm_kernel<0><<<dim3(NQKV/128, MTOT/128), 256>>>(x, Wqkv, bqkv, nullptr, HID, NQKV);
    attn_kernel<<<MTOT, 128>>>();
    gemm_kernel<1><<<dim3(HID/128, MTOT/128), 256>>>(nullptr, Wproj, bproj, out, HID, HID);
}

// round 4
// speedup vs baseline: 1.5779x; 1.5779x over previous
#include <cuda_runtime.h>
#include <cstdint>

#define BATCH   4
#define SEQ     4096
#define HID     2048
#define NHEADS  16
#define HDIM    128
#define MTOT    (BATCH*SEQ)   /* 16384 */
#define NQKV    (3*HID)       /* 6144  */

// ---------------- scratch (device globals; no runtime alloc) ----------------
__device__ float g_xr [(size_t)MTOT*HID];    // tf32-rounded x
__device__ float g_qkv[(size_t)MTOT*NQKV];   // qkv rows
__device__ float g_ctx[(size_t)MTOT*HID];    // permuted context (tf32-rounded)
__device__ float g_WT1[(size_t)NQKV*HID];    // Wqkv^T  [6144][2048], tf32-rounded
__device__ float g_WT2[(size_t)HID*HID];     // Wproj^T [2048][2048], tf32-rounded

// ---------------- helpers ----------------
__device__ __forceinline__ float tf32r(float x){
    unsigned u; asm("cvt.rna.tf32.f32 %0, %1;" : "=r"(u) : "f"(x));
    return __uint_as_float(u);
}
__device__ __forceinline__ uint32_t smem_u32(const void* p){
    uint32_t a;
    asm("{ .reg .u64 t; cvta.to.shared.u64 t, %1; cvt.u32.u64 %0, t; }"
        : "=r"(a) : "l"(p));
    return a;
}
__device__ __forceinline__ void cp_async16(uint32_t dst, const void* src){
    asm volatile("cp.async.cg.shared.global [%0], [%1], 16;"
                 :: "r"(dst), "l"(src));
}
#define LDSM4(rr, addr) \
    asm volatile("ldmatrix.sync.aligned.m8n8.x4.shared.b16 {%0,%1,%2,%3}, [%4];" \
        : "=r"((rr)[0]),"=r"((rr)[1]),"=r"((rr)[2]),"=r"((rr)[3]) : "r"(addr))

__device__ __forceinline__ void mma8u(float* c, const uint32_t* a,
                                      uint32_t b0, uint32_t b1){
    asm volatile("mma.sync.aligned.m16n8k8.row.col.f32.tf32.tf32.f32 "
        "{%0,%1,%2,%3},{%4,%5,%6,%7},{%8,%9},{%0,%1,%2,%3};"
        : "+f"(c[0]),"+f"(c[1]),"+f"(c[2]),"+f"(c[3])
        : "r"(a[0]),"r"(a[1]),"r"(a[2]),"r"(a[3]), "r"(b0),"r"(b1));
}

// ---------------------------------------------------------------------------
// TF32 mma.sync GEMM with ldmatrix fragment feed + cp.async pipeline.
// C[M x N] = A[M x K] * BT[N x K]^T + bias. CTA tile 128x128, KC=32, 3 stages.
// A and BT must be pre-rounded to tf32.
// ---------------------------------------------------------------------------
#define ROWB      144                 /* bytes per smem row (36 floats) */
#define STG_BYTES (256*ROWB)          /* 36864: 128 A-rows + 128 B-rows */
#define STAGES    3

__global__ void __launch_bounds__(256, 2)
tc_gemm(const float* __restrict__ A, const float* __restrict__ BT,
        const float* __restrict__ bias, float* __restrict__ C,
        int K, int N)
{
    extern __shared__ char dsm[];
    const uint32_t smem = smem_u32(dsm);
    const int tid = threadIdx.x, warp = tid>>5, lane = tid&31;
    const int g = lane>>2, t = lane&3;
    const int wm = warp>>2, wn = warp&3;             // 2 x 4 warps, 64x32 each
    const int m0 = blockIdx.y*128, n0 = blockIdx.x*128;
    const int NCH = K/32;

    const float* Ab = A  + (size_t)m0*K;
    const float* Bb = BT + (size_t)n0*K;

    // ldmatrix per-lane base offsets (4 matrices per x4)
    const int m8 = lane>>3, r8 = lane&7;
    const uint32_t aoff = (uint32_t)((wm*64 + (m8&1)*8 + r8)*ROWB + (m8>>1)*16);
    const uint32_t boff = (uint32_t)(128*ROWB + (wn*32 + (m8>>1)*8 + r8)*ROWB + (m8&1)*16);

    float acc[4][4][4];
    #pragma unroll
    for(int i=0;i<4;++i)
        #pragma unroll
        for(int j=0;j<4;++j)
            #pragma unroll
            for(int e=0;e<4;++e) acc[i][j][e]=0.f;

    auto load_chunk = [&](int c, int s){
        const uint32_t base = smem + s*STG_BYTES;
        const float* Ag = Ab + c*32;
        const float* Bg = Bb + c*32;
        #pragma unroll
        for(int i=0;i<4;++i){
            int seg = tid + 256*i;                   // A: 128 rows x 8 segs
            int r = seg>>3, sc = (seg&7)<<4;
            cp_async16(base + r*ROWB + sc, (const char*)(Ag + (size_t)r*K) + sc);
        }
        #pragma unroll
        for(int i=0;i<4;++i){
            int seg = tid + 256*i;                   // B: 128 rows x 8 segs
            int r = seg>>3, sc = (seg&7)<<4;
            cp_async16(base + 128*ROWB + r*ROWB + sc,
                       (const char*)(Bg + (size_t)r*K) + sc);
        }
        asm volatile("cp.async.commit_group;" ::: "memory");
    };

    load_chunk(0,0); load_chunk(1,1); load_chunk(2,2);

    int s = 0;
    for(int c=0;c<NCH;++c){
        int rem = NCH-1-c; if (rem > 2) rem = 2;
        switch(rem){
            case 2:  asm volatile("cp.async.wait_group 2;" ::: "memory"); break;
            case 1:  asm volatile("cp.async.wait_group 1;" ::: "memory"); break;
            default: asm volatile("cp.async.wait_group 0;" ::: "memory"); break;
        }
        __syncthreads();

        const uint32_t aA = smem + s*STG_BYTES + aoff;
        const uint32_t bA = smem + s*STG_BYTES + boff;
        #pragma unroll
        for(int ks=0; ks<4; ++ks){
            uint32_t af[4][4], bf[2][4];
            #pragma unroll
            for(int i=0;i<4;++i) LDSM4(af[i], aA + i*(16*ROWB) + ks*32);
            #pragma unroll
            for(int jp=0;jp<2;++jp) LDSM4(bf[jp], bA + jp*(16*ROWB) + ks*32);
            #pragma unroll
            for(int i=0;i<4;++i){
                mma8u(acc[i][0], af[i], bf[0][0], bf[0][1]);
                mma8u(acc[i][1], af[i], bf[0][2], bf[0][3]);
                mma8u(acc[i][2], af[i], bf[1][0], bf[1][1]);
                mma8u(acc[i][3], af[i], bf[1][2], bf[1][3]);
            }
        }
        __syncthreads();
        if (c+3 < NCH) load_chunk(c+3, s);
        s = (s==STAGES-1) ? 0 : s+1;
    }

    // epilogue: direct float2 stores + bias
    #pragma unroll
    for(int i=0;i<4;++i){
        #pragma unroll
        for(int j=0;j<4;++j){
            int r0 = m0 + wm*64 + i*16 + g;
            int c0 = n0 + wn*32 + j*8 + 2*t;
            float2 b01 = make_float2(bias[c0], bias[c0+1]);
            float2 v0 = make_float2(acc[i][j][0]+b01.x, acc[i][j][1]+b01.y);
            float2 v1 = make_float2(acc[i][j][2]+b01.x, acc[i][j][3]+b01.y);
            *(float2*)(C + (size_t)r0*N + c0)     = v0;
            *(float2*)(C + (size_t)(r0+8)*N + c0) = v1;
        }
    }
}

// ---------------------------------------------------------------------------
// prepass: round x to tf32 (rna)
// ---------------------------------------------------------------------------
__global__ void __launch_bounds__(1024)
round_kernel(const float* __restrict__ x, float* __restrict__ y, int n4)
{
    int i = blockIdx.x*blockDim.x + threadIdx.x;
    if (i < n4){
        float4 v = ((const float4*)x)[i];
        v.x=tf32r(v.x); v.y=tf32r(v.y); v.z=tf32r(v.z); v.w=tf32r(v.w);
        ((float4*)y)[i] = v;
    }
}

// ---------------------------------------------------------------------------
// prepass: transpose + round. W[K][N] -> WT[N][K]
// ---------------------------------------------------------------------------
__global__ void __launch_bounds__(256)
transpose_kernel(const float* __restrict__ W, float* __restrict__ WT,
                 int K, int N)
{
    __shared__ float tbuf[32][33];
    const int n0 = blockIdx.x*32, k0 = blockIdx.y*32;
    const int tx = threadIdx.x & 31, ty = threadIdx.x >> 5;  // 32 x 8
    #pragma unroll
    for(int i=0;i<4;++i)
        tbuf[ty+8*i][tx] = W[(size_t)(k0+ty+8*i)*N + n0+tx];
    __syncthreads();
    #pragma unroll
    for(int i=0;i<4;++i)
        WT[(size_t)(n0+ty+8*i)*K + k0+tx] = tf32r(tbuf[tx][ty+8*i]);
}

// ---------------------------------------------------------------------------
// Per-position head-mixing attention (reference einsum semantics).
// Writes g_ctx tf32-rounded, in transpose(0,2,1,3).reshape layout.
// ---------------------------------------------------------------------------
__global__ void __launch_bounds__(128)
attn_kernel()
{
    __shared__ float S[48*132];

    const int tid = threadIdx.x;
    const size_t pos = blockIdx.x;               // b*4096 + s
    const float* row = g_qkv + pos*NQKV;

    #pragma unroll
    for(int it=0; it<12; ++it){
        int idx = tid + 128*it;
        int f = idx<<2;
        int r = f>>7, c = f&127;
        *(float4*)(S + r*132 + c) = *(const float4*)(row + f);
    }
    __syncthreads();

    const int h = tid>>3, i = tid&7;
    const float4* Q4 = (const float4*)(S + h*132);
    const float4* K0 = (const float4*)(S + (16+i)*132);
    const float4* K1 = (const float4*)(S + (24+i)*132);

    float s0=0.f, s1=0.f;
    #pragma unroll
    for(int d=0; d<32; ++d){
        float4 q = Q4[d], a = K0[d], b = K1[d];
        s0 += q.x*a.x + q.y*a.y + q.z*a.z + q.w*a.w;
        s1 += q.x*b.x + q.y*b.y + q.z*b.z + q.w*b.w;
    }
    const float sc = 0.08838834764831845f;       // 1/sqrt(128)
    s0 *= sc; s1 *= sc;

    float m = fmaxf(s0, s1);
    m = fmaxf(m, __shfl_xor_sync(0xffffffffu, m, 1));
    m = fmaxf(m, __shfl_xor_sync(0xffffffffu, m, 2));
    m = fmaxf(m, __shfl_xor_sync(0xffffffffu, m, 4));
    float e0 = __expf(s0 - m), e1 = __expf(s1 - m);
    float sum = e0 + e1;
    sum += __shfl_xor_sync(0xffffffffu, sum, 1);
    sum += __shfl_xor_sync(0xffffffffu, sum, 2);
    sum += __shfl_xor_sync(0xffffffffu, sum, 4);
    float inv = 1.f/sum;
    float w0 = e0*inv, w1 = e1*inv;

    float wv[16];
    #pragma unroll
    for(int j=0;j<8;++j){
        wv[j]   = __shfl_sync(0xffffffffu, w0, j, 8);
        wv[j+8] = __shfl_sync(0xffffffffu, w1, j, 8);
    }

    const int b = (int)(pos>>12), s = (int)(pos&4095);
    float* orow = g_ctx + ((size_t)(b*SEQ + h*256 + (s>>4)))*HID + (size_t)(s&15)*HDIM;
    #pragma unroll
    for(int j=0;j<4;++j){
        int d4 = i + 8*j;
        float4 acc = make_float4(0.f,0.f,0.f,0.f);
        #pragma unroll
        for(int tt=0;tt<16;++tt){
            float4 v = *(const float4*)(S + (32+tt)*132 + (d4<<2));
            acc.x += wv[tt]*v.x; acc.y += wv[tt]*v.y;
            acc.z += wv[tt]*v.z; acc.w += wv[tt]*v.w;
        }
        acc.x=tf32r(acc.x); acc.y=tf32r(acc.y);
        acc.z=tf32r(acc.z); acc.w=tf32r(acc.w);
        *(float4*)(orow + (d4<<2)) = acc;
    }
}

// ---------------------------------------------------------------------------
extern "C" void kernel_launch(void* const* d_in, const int* in_sizes, int n_in,
                              void* d_out, int out_size)
{
    const float* x     = (const float*)d_in[0];
    const float* Wqkv  = (const float*)d_in[1];
    const float* bqkv  = (const float*)d_in[2];
    const float* Wproj = (const float*)d_in[3];
    const float* bproj = (const float*)d_in[4];
    float* out = (float*)d_out;

    cudaFuncSetAttribute(tc_gemm, cudaFuncAttributeMaxDynamicSharedMemorySize,
                         STAGES*STG_BYTES);

    float *xr, *qkv, *ctx, *wt1, *wt2;
    cudaGetSymbolAddress((void**)&xr,  g_xr);
    cudaGetSymbolAddress((void**)&qkv, g_qkv);
    cudaGetSymbolAddress((void**)&ctx, g_ctx);
    cudaGetSymbolAddress((void**)&wt1, g_WT1);
    cudaGetSymbolAddress((void**)&wt2, g_WT2);

    const int n4 = MTOT*HID/4;
    round_kernel<<<(n4+1023)/1024, 1024>>>(x, xr, n4);
    transpose_kernel<<<dim3(NQKV/32, HID/32), 256>>>(Wqkv, wt1, HID, NQKV);
    transpose_kernel<<<dim3(HID/32,  HID/32), 256>>>(Wproj, wt2, HID, HID);

    tc_gemm<<<dim3(NQKV/128, MTOT/128), 256, STAGES*STG_BYTES>>>(
        xr, wt1, bqkv, qkv, HID, NQKV);
    attn_kernel<<<MTOT, 128>>>();
    tc_gemm<<<dim3(HID/128, MTOT/128), 256, STAGES*STG_BYTES>>>(
        ctx, wt2, bproj, out, HID, HID);
}